// round 15
// baseline (speedup 1.0000x reference)
#include <cuda_runtime.h>
#include <cuda_bf16.h>
#include <math.h>
#include <stdint.h>

#define NPTS 16384
#define CD   512
#define DIN  1024
#define DST  16
#define DBCW 64
#define MLPD 1024
#define NCH  128
#define TCH  128

// ================= scratch =================
__device__ __align__(16) float g_xm [NPTS*DIN];
__device__ __align__(16) float g_dbc[NPTS*DBCW];
__device__ __align__(16) float g_x1 [NPTS*CD];    // also split-K scratch for x_proj partials
__device__ __align__(16) float g_An [DIN*DST];
__device__ __align__(16) float g_Hc [NCH*DIN*DST];
__device__ __align__(16) float g_sd [NCH*DIN];
__device__ __align__(16) float g_hi [NCH*DIN*DST];
// bf16 activations
__device__ __align__(16) __nv_bfloat16 g_u2  [NPTS*2*CD];    // [hi|lo]
__device__ __align__(16) __nv_bfloat16 g_xc1 [NPTS*DIN];     // plain bf16
__device__ __align__(16) __nv_bfloat16 g_z1  [NPTS*DIN];     // silu(z), bf16
__device__ __align__(16) __nv_bfloat16 g_y1  [NPTS*DIN];
__device__ __align__(16) __nv_bfloat16 g_h21 [NPTS*CD];
__device__ __align__(16) __nv_bfloat16 g_g1  [NPTS*MLPD];
// weights
__device__ __align__(16) __nv_bfloat16 g_xmw2 [1024*2*512];  // [hi|hi]
__device__ __align__(16) __nv_bfloat16 g_xpw1 [64*1024];     // plain bf16
__device__ __align__(16) __nv_bfloat16 g_zw1  [1024*512];
__device__ __align__(16) __nv_bfloat16 g_outw1[512*1024];
__device__ __align__(16) __nv_bfloat16 g_fw11 [1024*512];
__device__ __align__(16) __nv_bfloat16 g_fw21 [512*1024];

// ================= helpers =================
__device__ __forceinline__ uint32_t smem_u32(const void* p) {
    uint32_t a;
    asm("{ .reg .u64 t; cvta.to.shared.u64 t, %1; cvt.u32.u64 %0, t; }" : "=r"(a) : "l"(p));
    return a;
}
__device__ __forceinline__ void cp16(uint32_t dst, const void* src) {
    asm volatile("cp.async.cg.shared.global [%0], [%1], 16;" :: "r"(dst), "l"(src) : "memory");
}
#define CP_COMMIT() asm volatile("cp.async.commit_group;" ::: "memory")
#define CP_WAIT(n)  asm volatile("cp.async.wait_group %0;" :: "n"(n) : "memory")
#define LDSM4(r0, r1, r2, r3, addr) \
    asm volatile("ldmatrix.sync.aligned.m8n8.x4.shared.b16 {%0,%1,%2,%3}, [%4];" \
        : "=r"(r0), "=r"(r1), "=r"(r2), "=r"(r3) : "r"(addr))
#define MMA16816(c, a, b) \
    asm volatile("mma.sync.aligned.m16n8k16.row.col.f32.bf16.bf16.f32 " \
        "{%0,%1,%2,%3}, {%4,%5,%6,%7}, {%8,%9}, {%0,%1,%2,%3};" \
        : "+f"((c)[0]), "+f"((c)[1]), "+f"((c)[2]), "+f"((c)[3]) \
        : "r"((a)[0]), "r"((a)[1]), "r"((a)[2]), "r"((a)[3]), "r"((b)[0]), "r"((b)[1]))

__device__ __forceinline__ uint32_t swz(uint32_t off) { return off ^ ((off >> 3) & 0x70); }
__device__ __forceinline__ void bsplit(float x, unsigned short& h, unsigned short& l) {
    __nv_bfloat16 hb = __float2bfloat16(x);
    __nv_bfloat16 lb = __float2bfloat16(x - __bfloat162float(hb));
    h = __bfloat16_as_ushort(hb);
    l = __bfloat16_as_ushort(lb);
}
__device__ __forceinline__ uint32_t pk2(unsigned short a, unsigned short b) {
    return (uint32_t)a | ((uint32_t)b << 16);
}
__device__ __forceinline__ uint32_t pkf2(float a, float b) {
    return pk2(__bfloat16_as_ushort(__float2bfloat16(a)),
               __bfloat16_as_ushort(__float2bfloat16(b)));
}

// ================= bf16 tensor-core GEMM (mma.sync HMMA), 3-stage pipeline =================
// C[16384, Nn] = A @ B^T over K3 cols. SPLITK via blockIdx.z (contiguous K partitions).
// EPI: 0 fp32 | 3 bias+gelu->bf16 | 4 bias+res+scatter | 5 silu->bf16 | 6 gathered-res fp32
template<int BN, int EPI, int SPLITK>
__global__ __launch_bounds__(256) void tgemm(
    const __nv_bfloat16* __restrict__ A, int lda,
    const __nv_bfloat16* __restrict__ B, int ldb, int K3,
    float* __restrict__ C, int ldc,
    const float* __restrict__ bias, const float* __restrict__ res,
    const int* __restrict__ gmap, __nv_bfloat16* __restrict__ C3, int c3N)
{
    constexpr int WN  = BN / 2;
    constexpr int NT8 = WN / 8;
    constexpr int STAGE = (128 + BN) * 128;

    extern __shared__ char dsm[];
    uint32_t base = (smem_u32(dsm) + 1023) & ~1023u;

    const int tid = threadIdx.x;
    const int wid = tid >> 5, lid = tid & 31;
    const int m0 = blockIdx.y * 128;
    const int n0 = blockIdx.x * BN;
    const int wm = (wid >> 1) * 32;
    const int wn = (wid & 1) * WN;
    const int Kc = K3 / SPLITK;
    const int KB = Kc >> 6;
    if (SPLITK > 1) {
        int kz = blockIdx.z;
        A += kz * Kc;
        B += kz * Kc;
        C += (size_t)kz * NPTS * ldc;
    }

    float acc[2][NT8][4];
#pragma unroll
    for (int mt = 0; mt < 2; mt++)
#pragma unroll
        for (int nt = 0; nt < NT8; nt++)
#pragma unroll
            for (int j = 0; j < 4; j++) acc[mt][nt][j] = 0.f;

    auto load_stage = [&](int kb, int buf) {
        uint32_t sA = base + buf * STAGE;
        uint32_t sB = sA + 16384;
        const __nv_bfloat16* Ab = A + (size_t)m0 * lda + kb * 64;
        const __nv_bfloat16* Bb = B + (size_t)n0 * ldb + kb * 64;
#pragma unroll
        for (int i = tid; i < 1024; i += 256) {
            int row = i >> 3, c = i & 7;
            uint32_t off = (row << 7) + (c << 4);
            cp16(sA + swz(off), Ab + (size_t)row * lda + c * 8);
        }
#pragma unroll
        for (int i = tid; i < BN * 8; i += 256) {
            int row = i >> 3, c = i & 7;
            uint32_t off = (row << 7) + (c << 4);
            cp16(sB + swz(off), Bb + (size_t)row * ldb + c * 8);
        }
        CP_COMMIT();
    };

    const int lr = lid & 7, lg = lid >> 3;
    const int rsel = (lg & 1) * 8 + lr;
    const int ksel = (lg >> 1) * 8;

    load_stage(0, 0);
    if (KB > 1) load_stage(1, 1);

    for (int kb = 0; kb < KB; kb++) {
        if (kb + 1 < KB) CP_WAIT(1);
        else             CP_WAIT(0);
        __syncthreads();
        if (kb + 2 < KB) load_stage(kb + 2, (kb + 2) % 3);

        uint32_t sA = base + (kb % 3) * STAGE;
        uint32_t sB = sA + 16384;
#pragma unroll
        for (int ks = 0; ks < 4; ks++) {
            uint32_t a[2][4];
#pragma unroll
            for (int mt = 0; mt < 2; mt++) {
                uint32_t off = (uint32_t)(wm + mt * 16 + rsel) * 128 + (ks * 16 + ksel) * 2;
                LDSM4(a[mt][0], a[mt][1], a[mt][2], a[mt][3], sA + swz(off));
            }
            uint32_t b[NT8][2];
#pragma unroll
            for (int nt2 = 0; nt2 < NT8 / 2; nt2++) {
                uint32_t off = (uint32_t)(wn + nt2 * 16 + rsel) * 128 + (ks * 16 + ksel) * 2;
                uint32_t r0, r1, r2, r3;
                LDSM4(r0, r1, r2, r3, sB + swz(off));
                b[2*nt2][0] = r0; b[2*nt2][1] = r2;
                b[2*nt2+1][0] = r1; b[2*nt2+1][1] = r3;
            }
#pragma unroll
            for (int mt = 0; mt < 2; mt++)
#pragma unroll
                for (int nt = 0; nt < NT8; nt++)
                    MMA16816(acc[mt][nt], a[mt], b[nt]);
        }
    }

    // ---------------- epilogue ----------------
    const int tg = lid >> 2, tq = lid & 3;
#pragma unroll
    for (int mt = 0; mt < 2; mt++) {
#pragma unroll
        for (int half = 0; half < 2; half++) {
            const int m = m0 + wm + mt * 16 + half * 8 + tg;
            const int orow = (EPI == 4) ? gmap[m] : m;
            const int rrow = (EPI == 6) ? gmap[m] : m;
#pragma unroll
            for (int nt = 0; nt < NT8; nt++) {
                const int n = n0 + wn + nt * 8 + tq * 2;
                float v0 = acc[mt][nt][half * 2 + 0];
                float v1 = acc[mt][nt][half * 2 + 1];
                if (EPI == 3 || EPI == 4) {
                    float2 bb = *(const float2*)(bias + n);
                    v0 += bb.x; v1 += bb.y;
                }
                if (EPI == 4 || EPI == 6) {
                    float2 rr = *(const float2*)(res + (size_t)rrow * ldc + n);
                    v0 += rr.x; v1 += rr.y;
                }
                if (EPI == 3 || EPI == 5) {
                    if (EPI == 3) {
                        v0 = 0.5f * v0 * (1.f + erff(v0 * 0.70710678118654752f));
                        v1 = 0.5f * v1 * (1.f + erff(v1 * 0.70710678118654752f));
                    } else {
                        v0 = v0 / (1.f + __expf(-v0));
                        v1 = v1 / (1.f + __expf(-v1));
                    }
                    __nv_bfloat16* row1 = C3 + (size_t)m * c3N;
                    *(uint32_t*)(row1 + n) = pkf2(v0, v1);
                } else {
                    *(float2*)(C + (size_t)orow * ldc + n) = make_float2(v0, v1);
                }
            }
        }
    }
}

// ================= fused weight prep (all conversions + A) =================
__global__ void prep(const float* __restrict__ inpw, const float* __restrict__ xpw,
                     const float* __restrict__ outw,
                     const float* __restrict__ fw1, const float* __restrict__ fw2,
                     const float* __restrict__ alog)
{
    int idx = blockIdx.x * blockDim.x + threadIdx.x;
    const int N0 = 1024 * 1024;  // xm [hi|hi]
    const int N1 = 64 * 1024;    // x_proj plain
    const int N2 = 1024 * 512;   // z plain
    const int N3 = 512 * 1024;   // out_proj plain
    const int N4 = 1024 * 512;   // ffn1^T
    const int N5 = 512 * 1024;   // ffn2^T
    const int N6 = DIN * DST;    // An
    unsigned short h, l;
    if (idx < N0) {
        int n = idx >> 10, c = idx & 1023;
        int k = (c < 512) ? c : (c - 512);
        bsplit(inpw[(size_t)n * 512 + k], h, l);
        g_xmw2[idx] = __ushort_as_bfloat16(h);
    } else if ((idx -= N0) < N1) {
        g_xpw1[idx] = __float2bfloat16(xpw[idx]);
    } else if ((idx -= N1) < N2) {
        g_zw1[idx] = __float2bfloat16(inpw[(size_t)1024 * 512 + idx]);
    } else if ((idx -= N2) < N3) {
        g_outw1[idx] = __float2bfloat16(outw[idx]);
    } else if ((idx -= N3) < N4) {
        int n = idx / 512, k = idx - n * 512;
        g_fw11[idx] = __float2bfloat16(fw1[(size_t)k * 1024 + n]);
    } else if ((idx -= N4) < N5) {
        int n = idx / 1024, k = idx - n * 1024;
        g_fw21[idx] = __float2bfloat16(fw2[(size_t)k * 512 + n]);
    } else if ((idx -= N5) < N6) {
        g_An[idx] = -__expf(alog[idx]);
    }
}

// split-K reduce (2 partials in g_x1 scratch) -> dbc
__global__ void reduce2_kernel()
{
    int i = blockIdx.x * blockDim.x + threadIdx.x;   // NPTS*64
    const float* p = g_x1;
    const int S = NPTS * 64;
    g_dbc[i] = p[i] + p[i + S];
}

// ================= LayerNorm (+gather), segs=2 -> [hi|lo], segs=1 -> bf16 =================
__global__ __launch_bounds__(128) void ln_kernel(
    const float* __restrict__ in, const int* __restrict__ gidx,
    const float* __restrict__ w, const float* __restrict__ b,
    __nv_bfloat16* __restrict__ outb, int segs)
{
    int row = blockIdx.x;
    int src = gidx ? gidx[row] : row;
    float4 v = *((const float4*)(in + (size_t)src * CD) + threadIdx.x);
    float s  = v.x + v.y + v.z + v.w;
    float ss = v.x*v.x + v.y*v.y + v.z*v.z + v.w*v.w;
#pragma unroll
    for (int o = 16; o; o >>= 1) {
        s  += __shfl_xor_sync(0xffffffffu, s,  o);
        ss += __shfl_xor_sync(0xffffffffu, ss, o);
    }
    __shared__ float sh[10];
    if ((threadIdx.x & 31) == 0) {
        sh[threadIdx.x >> 5] = s;
        sh[4 + (threadIdx.x >> 5)] = ss;
    }
    __syncthreads();
    if (threadIdx.x == 0) {
        float S  = sh[0] + sh[1] + sh[2] + sh[3];
        float SS = sh[4] + sh[5] + sh[6] + sh[7];
        float mu = S * (1.f / CD);
        float var = SS * (1.f / CD) - mu * mu;
        sh[8] = mu;
        sh[9] = rsqrtf(var + 1e-5f);
    }
    __syncthreads();
    float mu = sh[8], r = sh[9];
    float4 wv = *((const float4*)w + threadIdx.x);
    float4 bv = *((const float4*)b + threadIdx.x);
    float o[4];
    o[0] = (v.x - mu) * r * wv.x + bv.x;
    o[1] = (v.y - mu) * r * wv.y + bv.y;
    o[2] = (v.z - mu) * r * wv.z + bv.z;
    o[3] = (v.w - mu) * r * wv.w + bv.w;
    unsigned short h[4], l[4];
#pragma unroll
    for (int j = 0; j < 4; j++) bsplit(o[j], h[j], l[j]);
    uint2 wh = make_uint2(pk2(h[0], h[1]), pk2(h[2], h[3]));
    __nv_bfloat16* rowp = outb + (size_t)row * (segs * CD) + 4 * threadIdx.x;
    *(uint2*)(rowp) = wh;
    if (segs == 2) {
        uint2 wl = make_uint2(pk2(l[0], l[1]), pk2(l[2], l[3]));
        *(uint2*)(rowp + CD) = wl;
    }
}

// ================= conv1d (k=4) + SiLU -> xc1 (plain bf16) =================
__global__ void conv_silu_kernel(const float* __restrict__ cw, const float* __restrict__ cb)
{
    int idx = blockIdx.x * blockDim.x + threadIdx.x;
    int t = idx >> 10, d = idx & 1023;
    float acc = cb[d];
#pragma unroll
    for (int k = 0; k < 4; k++) {
        int tt = t - 3 + k;
        if (tt >= 0) acc = fmaf(g_xm[(size_t)tt * DIN + d], cw[d * 4 + k], acc);
    }
    float sg = 1.f / (1.f + __expf(-acc));
    g_xc1[idx] = __float2bfloat16(acc * sg);
}

// ================= chunked selective scan (dt computed in-kernel) =================
__device__ __forceinline__ bool a_struct_fast(const float* Av)
{
    bool fast = true;
#pragma unroll
    for (int s = 1; s < DST; s++)
        fast = fast && (fabsf(Av[s] - (float)(s + 1) * Av[0]) <= 1e-3f * fabsf(Av[s]));
    return fast;
}
__device__ __forceinline__ void powers16(float p, float* a)
{
    float p2 = p * p, p4 = p2 * p2, p8 = p4 * p4;
    a[0] = p;        a[1] = p2;       a[2] = p2 * p;   a[3] = p4;
    a[4] = p4 * p;   a[5] = p4 * p2;  a[6] = p4 * a[2]; a[7] = p8;
    a[8] = p8 * p;   a[9] = p8 * p2;  a[10] = p8 * a[2]; a[11] = p8 * p4;
    a[12] = p8 * a[4]; a[13] = p8 * a[5]; a[14] = p8 * a[6]; a[15] = p8 * p8;
}
__device__ __forceinline__ float xc_at(int t, int d)
{
    return __bfloat162float(g_xc1[(size_t)t * DIN + d]);
}
__device__ __forceinline__ float softplus_f(float x)
{
    float e = __expf(-fabsf(x));
    return fmaxf(x, 0.f) + __logf(1.f + e);
}

// pass1: chunk summaries only (final state Hc, sum dt); dt fused
__global__ __launch_bounds__(128) void scan_pass1_kernel(
    const float* __restrict__ dtw, const float* __restrict__ dtb)
{
    const int tid = threadIdx.x;
    const int d = blockIdx.x * 128 + tid;
    const int c = blockIdx.y;
    const int t0 = c * TCH;
    __shared__ float Bsh[TCH][DST];
    __shared__ float Dsh[TCH][32];
    __shared__ float wDt[32][128];
    for (int i = tid; i < TCH * DST; i += 128) {
        int t = i >> 4, s = i & 15;
        Bsh[t][s] = g_dbc[(size_t)(t0 + t) * DBCW + 32 + s];
    }
    for (int i = tid; i < TCH * 32; i += 128) {
        int t = i >> 5, k = i & 31;
        Dsh[t][k] = g_dbc[(size_t)(t0 + t) * DBCW + k];
    }
    for (int i = tid; i < 32 * 128; i += 128) {
        int k = i >> 7, j = i & 127;
        wDt[k][j] = dtw[(size_t)(blockIdx.x * 128 + j) * 32 + k];
    }
    __syncthreads();
    float Av[DST], h[DST];
#pragma unroll
    for (int s = 0; s < DST; s++) { Av[s] = g_An[d * DST + s]; h[s] = 0.f; }
    const float bias_d = dtb[d];
    float dts = 0.f;
    bool fast = a_struct_fast(Av);
    for (int t = 0; t < TCH; t++) {
        float acc = bias_d;
#pragma unroll
        for (int k = 0; k < 32; k++)
            acc = fmaf(Dsh[t][k], wDt[k][tid], acc);
        float dtv = softplus_f(acc);
        float dtx = dtv * xc_at(t0 + t, d);
        dts += dtv;
        if (fast) {
            float a[DST];
            powers16(__expf(dtv * Av[0]), a);
#pragma unroll
            for (int s = 0; s < DST; s++)
                h[s] = fmaf(a[s], h[s], dtx * Bsh[t][s]);
        } else {
#pragma unroll
            for (int s = 0; s < DST; s++)
                h[s] = fmaf(__expf(dtv * Av[s]), h[s], dtx * Bsh[t][s]);
        }
    }
#pragma unroll
    for (int s = 0; s < DST; s++)
        g_Hc[((size_t)c * DIN + d) * DST + s] = h[s];
    g_sd[(size_t)c * DIN + d] = dts;
}

__global__ void scan_combine_kernel()
{
    int idx = blockIdx.x * blockDim.x + threadIdx.x;
    int d = idx >> 4;
    float Av = g_An[idx];
    float h = 0.f;
    g_hi[idx] = 0.f;
    for (int c = 1; c < NCH; c++) {
        h = fmaf(__expf(Av * g_sd[(size_t)(c - 1) * DIN + d]), h,
                 g_Hc[(size_t)(c - 1) * DIN * DST + idx]);
        g_hi[(size_t)c * DIN * DST + idx] = h;
    }
}

// pass2: full recurrence from h_init + fused gate -> y1 (bf16); dt fused
__global__ __launch_bounds__(128) void scan_pass2_kernel(
    const float* __restrict__ dtw, const float* __restrict__ dtb,
    const float* __restrict__ Dskip)
{
    const int tid = threadIdx.x;
    const int d = blockIdx.x * 128 + tid;
    const int c = blockIdx.y;
    const int t0 = c * TCH;
    __shared__ float Bsh[TCH][DST];
    __shared__ float Csh[TCH][DST];
    __shared__ float Dsh[TCH][32];
    __shared__ float wDt[32][128];
    for (int i = tid; i < TCH * DST; i += 128) {
        int t = i >> 4, s = i & 15;
        Bsh[t][s] = g_dbc[(size_t)(t0 + t) * DBCW + 32 + s];
        Csh[t][s] = g_dbc[(size_t)(t0 + t) * DBCW + 48 + s];
    }
    for (int i = tid; i < TCH * 32; i += 128) {
        int t = i >> 5, k = i & 31;
        Dsh[t][k] = g_dbc[(size_t)(t0 + t) * DBCW + k];
    }
    for (int i = tid; i < 32 * 128; i += 128) {
        int k = i >> 7, j = i & 127;
        wDt[k][j] = dtw[(size_t)(blockIdx.x * 128 + j) * 32 + k];
    }
    __syncthreads();
    float Av[DST], h[DST];
#pragma unroll
    for (int s = 0; s < DST; s++) {
        Av[s] = g_An[d * DST + s];
        h[s]  = g_hi[(size_t)c * DIN * DST + d * DST + s];
    }
    const float bias_d = dtb[d];
    const float Dv = Dskip[d];
    bool fast = a_struct_fast(Av);
    for (int t = 0; t < TCH; t++) {
        float acc = bias_d;
#pragma unroll
        for (int k = 0; k < 32; k++)
            acc = fmaf(Dsh[t][k], wDt[k][tid], acc);
        float dtv = softplus_f(acc);
        float xv  = xc_at(t0 + t, d);
        float dtx = dtv * xv;
        float y = 0.f;
        if (fast) {
            float a[DST];
            powers16(__expf(dtv * Av[0]), a);
#pragma unroll
            for (int s = 0; s < DST; s++) {
                h[s] = fmaf(a[s], h[s], dtx * Bsh[t][s]);
                y = fmaf(h[s], Csh[t][s], y);
            }
        } else {
#pragma unroll
            for (int s = 0; s < DST; s++) {
                h[s] = fmaf(__expf(dtv * Av[s]), h[s], dtx * Bsh[t][s]);
                y = fmaf(h[s], Csh[t][s], y);
            }
        }
        float sg = __bfloat162float(g_z1[(size_t)(t0 + t) * DIN + d]);
        float val = (y + xv * Dv) * sg;
        g_y1[(size_t)(t0 + t) * DIN + d] = __float2bfloat16(val);
    }
}

// ================= launch =================
extern "C" void kernel_launch(void* const* d_in, const int* in_sizes, int n_in,
                              void* d_out, int out_size)
{
    (void)in_sizes; (void)n_in; (void)out_size;
    const float* feat  = (const float*)d_in[0];
    const int*   order = (const int*)  d_in[1];
    const float* ln1w  = (const float*)d_in[3];
    const float* ln1b  = (const float*)d_in[4];
    const float* inpw  = (const float*)d_in[5];
    const float* convw = (const float*)d_in[6];
    const float* convb = (const float*)d_in[7];
    const float* xpw   = (const float*)d_in[8];
    const float* dtw   = (const float*)d_in[9];
    const float* dtb   = (const float*)d_in[10];
    const float* alog  = (const float*)d_in[11];
    const float* dskip = (const float*)d_in[12];
    const float* outw  = (const float*)d_in[13];
    const float* ln2w  = (const float*)d_in[14];
    const float* ln2b  = (const float*)d_in[15];
    const float* fw1   = (const float*)d_in[16];
    const float* fb1   = (const float*)d_in[17];
    const float* fw2   = (const float*)d_in[18];
    const float* fb2   = (const float*)d_in[19];
    float* out = (float*)d_out;

    const int SM128 = 3 * (128 + 128) * 128 + 1024;  // 99328
    const int SM64  = 3 * (128 + 64)  * 128 + 1024;  // 74752
    cudaFuncSetAttribute(tgemm<128,0,1>, cudaFuncAttributeMaxDynamicSharedMemorySize, SM128);
    cudaFuncSetAttribute(tgemm<64,0,2>,  cudaFuncAttributeMaxDynamicSharedMemorySize, SM64);
    cudaFuncSetAttribute(tgemm<128,3,1>, cudaFuncAttributeMaxDynamicSharedMemorySize, SM128);
    cudaFuncSetAttribute(tgemm<128,4,1>, cudaFuncAttributeMaxDynamicSharedMemorySize, SM128);
    cudaFuncSetAttribute(tgemm<128,5,1>, cudaFuncAttributeMaxDynamicSharedMemorySize, SM128);
    cudaFuncSetAttribute(tgemm<128,6,1>, cudaFuncAttributeMaxDynamicSharedMemorySize, SM128);

    void *pxm, *px1;
    void *pu2, *pxc1, *pz1, *py1, *ph21, *pg1;
    void *pw0, *pwz, *pw1, *pw3, *pw4, *pw5;
    cudaGetSymbolAddress(&pxm,  g_xm);
    cudaGetSymbolAddress(&px1,  g_x1);
    cudaGetSymbolAddress(&pu2,  g_u2);
    cudaGetSymbolAddress(&pxc1, g_xc1);
    cudaGetSymbolAddress(&pz1,  g_z1);
    cudaGetSymbolAddress(&py1,  g_y1);
    cudaGetSymbolAddress(&ph21, g_h21);
    cudaGetSymbolAddress(&pg1,  g_g1);
    cudaGetSymbolAddress(&pw0,  g_xmw2);
    cudaGetSymbolAddress(&pwz,  g_zw1);
    cudaGetSymbolAddress(&pw1,  g_xpw1);
    cudaGetSymbolAddress(&pw3,  g_outw1);
    cudaGetSymbolAddress(&pw4,  g_fw11);
    cudaGetSymbolAddress(&pw5,  g_fw21);

    // [0] fused weight prep
    prep<<<12608, 256>>>(inpw, xpw, outw, fw1, fw2, alog);
    // [1] gather + LN1 -> u2 (bf16 [hi|lo])
    ln_kernel<<<NPTS, 128>>>(feat, order, ln1w, ln1b, (__nv_bfloat16*)pu2, 2);
    // [2] xm = u @ in_proj_xm^T  (K=1024: [ah|al]·[bh|bh]) -> g_xm
    tgemm<128,0,1><<<dim3(8,128), 256, SM128>>>((__nv_bfloat16*)pu2, 1024, (__nv_bfloat16*)pw0, 1024, 1024,
                                                (float*)pxm, DIN, nullptr, nullptr, nullptr, nullptr, 0);
    // [3] z1 = silu(u @ in_proj_z^T) -> bf16   <-- ncu capture target
    tgemm<128,5,1><<<dim3(8,128), 256, SM128>>>((__nv_bfloat16*)pu2, 1024, (__nv_bfloat16*)pwz, 512, 512,
                                                nullptr, DIN, nullptr, nullptr, nullptr, (__nv_bfloat16*)pz1, DIN);
    // [4] conv + SiLU -> xc1 (plain bf16)
    conv_silu_kernel<<<(NPTS*DIN)/256, 256>>>(convw, convb);
    // [5] dbc partials = xc @ x_proj^T  (plain bf16, split-K x2 -> g_x1 scratch)
    tgemm<64,0,2><<<dim3(1,128,2), 256, SM64>>>((__nv_bfloat16*)pxc1, 1024, (__nv_bfloat16*)pw1, 1024, 1024,
                                                (float*)px1, DBCW, nullptr, nullptr, nullptr, nullptr, 0);
    // [6] reduce partials -> dbc
    reduce2_kernel<<<(NPTS*DBCW)/256, 256>>>();
    // [7-9] chunked selective scan with fused dt
    scan_pass1_kernel<<<dim3(DIN/128, NCH), 128>>>(dtw, dtb);
    scan_combine_kernel<<<(DIN*DST)/256, 256>>>();
    scan_pass2_kernel<<<dim3(DIN/128, NCH), 128>>>(dtw, dtb, dskip);
    // [10] x1 = feat[order[m]] + y @ out_proj^T  (gathered residual, fp32)
    tgemm<128,6,1><<<dim3(4,128), 256, SM128>>>((__nv_bfloat16*)py1, 1024, (__nv_bfloat16*)pw3, 1024, 1024,
                                                (float*)px1, CD, nullptr, feat, order, nullptr, 0);
    // [11] h2 = LN2(x1) -> plain bf16
    ln_kernel<<<NPTS, 128>>>((const float*)px1, nullptr, ln2w, ln2b, (__nv_bfloat16*)ph21, 1);
    // [12] g = gelu(h2 @ ffn_w1 + b1) -> plain bf16
    tgemm<128,3,1><<<dim3(8,128), 256, SM128>>>((__nv_bfloat16*)ph21, 512, (__nv_bfloat16*)pw4, 512, 512,
                                                nullptr, MLPD, fb1, nullptr, nullptr, (__nv_bfloat16*)pg1, MLPD);
    // [13] out[order[m]] = x1[m] + g @ ffn_w2 + b2  (fused residual + scatter)
    tgemm<128,4,1><<<dim3(4,128), 256, SM128>>>((__nv_bfloat16*)pg1, 1024, (__nv_bfloat16*)pw5, 1024, 1024,
                                                out, CD, fb2, (const float*)px1, order, nullptr, 0);
}

// round 16
// speedup vs baseline: 1.1583x; 1.1583x over previous
#include <cuda_runtime.h>
#include <cuda_bf16.h>
#include <math.h>
#include <stdint.h>

#define NPTS 16384
#define CD   512
#define DIN  1024
#define DST  16
#define DBCW 64
#define MLPD 1024
#define NCH  128
#define TCH  128

// ================= scratch =================
__device__ __align__(16) float g_xm [NPTS*DIN];
__device__ __align__(16) float g_dbc[NPTS*DBCW];
__device__ __align__(16) float g_x1 [NPTS*CD];    // also split-K scratch for x_proj partials
__device__ __align__(16) float g_An [DIN*DST];
__device__ __align__(16) float g_Hc [NCH*DIN*DST];
__device__ __align__(16) float g_sd [NCH*DIN];
__device__ __align__(16) float g_hi [NCH*DIN*DST];
// bf16 activations
__device__ __align__(16) __nv_bfloat16 g_u2  [NPTS*2*CD];    // [hi|lo]
__device__ __align__(16) __nv_bfloat16 g_xc1 [NPTS*DIN];     // plain bf16
__device__ __align__(16) __nv_bfloat16 g_dta1[NPTS*64];      // [dbc[:,0:32] bf16 | 0]
__device__ __align__(16) __nv_bfloat16 g_dt1 [NPTS*DIN];     // softplus(dt) bf16
__device__ __align__(16) __nv_bfloat16 g_z1  [NPTS*DIN];     // silu(z), bf16
__device__ __align__(16) __nv_bfloat16 g_y1  [NPTS*DIN];
__device__ __align__(16) __nv_bfloat16 g_h21 [NPTS*CD];
__device__ __align__(16) __nv_bfloat16 g_g1  [NPTS*MLPD];
// weights
__device__ __align__(16) __nv_bfloat16 g_xmw2 [1024*2*512];  // [hi|hi]
__device__ __align__(16) __nv_bfloat16 g_xpw1 [64*1024];     // plain bf16
__device__ __align__(16) __nv_bfloat16 g_dtw1 [1024*64];     // [w bf16 | 0]
__device__ __align__(16) __nv_bfloat16 g_zw1  [1024*512];
__device__ __align__(16) __nv_bfloat16 g_outw1[512*1024];
__device__ __align__(16) __nv_bfloat16 g_fw11 [1024*512];
__device__ __align__(16) __nv_bfloat16 g_fw21 [512*1024];

// ================= helpers =================
__device__ __forceinline__ uint32_t smem_u32(const void* p) {
    uint32_t a;
    asm("{ .reg .u64 t; cvta.to.shared.u64 t, %1; cvt.u32.u64 %0, t; }" : "=r"(a) : "l"(p));
    return a;
}
__device__ __forceinline__ void cp16(uint32_t dst, const void* src) {
    asm volatile("cp.async.cg.shared.global [%0], [%1], 16;" :: "r"(dst), "l"(src) : "memory");
}
#define CP_COMMIT() asm volatile("cp.async.commit_group;" ::: "memory")
#define CP_WAIT(n)  asm volatile("cp.async.wait_group %0;" :: "n"(n) : "memory")
#define LDSM4(r0, r1, r2, r3, addr) \
    asm volatile("ldmatrix.sync.aligned.m8n8.x4.shared.b16 {%0,%1,%2,%3}, [%4];" \
        : "=r"(r0), "=r"(r1), "=r"(r2), "=r"(r3) : "r"(addr))
#define MMA16816(c, a, b) \
    asm volatile("mma.sync.aligned.m16n8k16.row.col.f32.bf16.bf16.f32 " \
        "{%0,%1,%2,%3}, {%4,%5,%6,%7}, {%8,%9}, {%0,%1,%2,%3};" \
        : "+f"((c)[0]), "+f"((c)[1]), "+f"((c)[2]), "+f"((c)[3]) \
        : "r"((a)[0]), "r"((a)[1]), "r"((a)[2]), "r"((a)[3]), "r"((b)[0]), "r"((b)[1]))

__device__ __forceinline__ uint32_t swz(uint32_t off) { return off ^ ((off >> 3) & 0x70); }
__device__ __forceinline__ void bsplit(float x, unsigned short& h, unsigned short& l) {
    __nv_bfloat16 hb = __float2bfloat16(x);
    __nv_bfloat16 lb = __float2bfloat16(x - __bfloat162float(hb));
    h = __bfloat16_as_ushort(hb);
    l = __bfloat16_as_ushort(lb);
}
__device__ __forceinline__ uint32_t pk2(unsigned short a, unsigned short b) {
    return (uint32_t)a | ((uint32_t)b << 16);
}
__device__ __forceinline__ uint32_t pkf2(float a, float b) {
    return pk2(__bfloat16_as_ushort(__float2bfloat16(a)),
               __bfloat16_as_ushort(__float2bfloat16(b)));
}

// ================= bf16 tensor-core GEMM (mma.sync HMMA), 3-stage pipeline =================
// C[16384, Nn] = A @ B^T over K3 cols. SPLITK via blockIdx.z (contiguous K partitions).
// EPI: 0 fp32 | 1 bias+softplus->bf16 | 3 bias+gelu->bf16 | 4 bias+res+scatter | 5 silu->bf16 | 6 gathered-res fp32
template<int BN, int EPI, int SPLITK>
__global__ __launch_bounds__(256) void tgemm(
    const __nv_bfloat16* __restrict__ A, int lda,
    const __nv_bfloat16* __restrict__ B, int ldb, int K3,
    float* __restrict__ C, int ldc,
    const float* __restrict__ bias, const float* __restrict__ res,
    const int* __restrict__ gmap, __nv_bfloat16* __restrict__ C3, int c3N)
{
    constexpr int WN  = BN / 2;
    constexpr int NT8 = WN / 8;
    constexpr int STAGE = (128 + BN) * 128;

    extern __shared__ char dsm[];
    uint32_t base = (smem_u32(dsm) + 1023) & ~1023u;

    const int tid = threadIdx.x;
    const int wid = tid >> 5, lid = tid & 31;
    const int m0 = blockIdx.y * 128;
    const int n0 = blockIdx.x * BN;
    const int wm = (wid >> 1) * 32;
    const int wn = (wid & 1) * WN;
    const int Kc = K3 / SPLITK;
    const int KB = Kc >> 6;
    if (SPLITK > 1) {
        int kz = blockIdx.z;
        A += kz * Kc;
        B += kz * Kc;
        C += (size_t)kz * NPTS * ldc;
    }

    float acc[2][NT8][4];
#pragma unroll
    for (int mt = 0; mt < 2; mt++)
#pragma unroll
        for (int nt = 0; nt < NT8; nt++)
#pragma unroll
            for (int j = 0; j < 4; j++) acc[mt][nt][j] = 0.f;

    auto load_stage = [&](int kb, int buf) {
        uint32_t sA = base + buf * STAGE;
        uint32_t sB = sA + 16384;
        const __nv_bfloat16* Ab = A + (size_t)m0 * lda + kb * 64;
        const __nv_bfloat16* Bb = B + (size_t)n0 * ldb + kb * 64;
#pragma unroll
        for (int i = tid; i < 1024; i += 256) {
            int row = i >> 3, c = i & 7;
            uint32_t off = (row << 7) + (c << 4);
            cp16(sA + swz(off), Ab + (size_t)row * lda + c * 8);
        }
#pragma unroll
        for (int i = tid; i < BN * 8; i += 256) {
            int row = i >> 3, c = i & 7;
            uint32_t off = (row << 7) + (c << 4);
            cp16(sB + swz(off), Bb + (size_t)row * ldb + c * 8);
        }
        CP_COMMIT();
    };

    const int lr = lid & 7, lg = lid >> 3;
    const int rsel = (lg & 1) * 8 + lr;
    const int ksel = (lg >> 1) * 8;

    load_stage(0, 0);
    if (KB > 1) load_stage(1, 1);

    for (int kb = 0; kb < KB; kb++) {
        if (kb + 1 < KB) CP_WAIT(1);
        else             CP_WAIT(0);
        __syncthreads();
        if (kb + 2 < KB) load_stage(kb + 2, (kb + 2) % 3);

        uint32_t sA = base + (kb % 3) * STAGE;
        uint32_t sB = sA + 16384;
#pragma unroll
        for (int ks = 0; ks < 4; ks++) {
            uint32_t a[2][4];
#pragma unroll
            for (int mt = 0; mt < 2; mt++) {
                uint32_t off = (uint32_t)(wm + mt * 16 + rsel) * 128 + (ks * 16 + ksel) * 2;
                LDSM4(a[mt][0], a[mt][1], a[mt][2], a[mt][3], sA + swz(off));
            }
            uint32_t b[NT8][2];
#pragma unroll
            for (int nt2 = 0; nt2 < NT8 / 2; nt2++) {
                uint32_t off = (uint32_t)(wn + nt2 * 16 + rsel) * 128 + (ks * 16 + ksel) * 2;
                uint32_t r0, r1, r2, r3;
                LDSM4(r0, r1, r2, r3, sB + swz(off));
                b[2*nt2][0] = r0; b[2*nt2][1] = r2;
                b[2*nt2+1][0] = r1; b[2*nt2+1][1] = r3;
            }
#pragma unroll
            for (int mt = 0; mt < 2; mt++)
#pragma unroll
                for (int nt = 0; nt < NT8; nt++)
                    MMA16816(acc[mt][nt], a[mt], b[nt]);
        }
    }

    // ---------------- epilogue ----------------
    const int tg = lid >> 2, tq = lid & 3;
#pragma unroll
    for (int mt = 0; mt < 2; mt++) {
#pragma unroll
        for (int half = 0; half < 2; half++) {
            const int m = m0 + wm + mt * 16 + half * 8 + tg;
            const int orow = (EPI == 4) ? gmap[m] : m;
            const int rrow = (EPI == 6) ? gmap[m] : m;
#pragma unroll
            for (int nt = 0; nt < NT8; nt++) {
                const int n = n0 + wn + nt * 8 + tq * 2;
                float v0 = acc[mt][nt][half * 2 + 0];
                float v1 = acc[mt][nt][half * 2 + 1];
                if (EPI == 1 || EPI == 3 || EPI == 4) {
                    float2 bb = *(const float2*)(bias + n);
                    v0 += bb.x; v1 += bb.y;
                }
                if (EPI == 4 || EPI == 6) {
                    float2 rr = *(const float2*)(res + (size_t)rrow * ldc + n);
                    v0 += rr.x; v1 += rr.y;
                }
                if (EPI == 1 || EPI == 3 || EPI == 5) {
                    if (EPI == 1) {
                        v0 = (v0 > 0.f) ? (v0 + log1pf(__expf(-v0))) : log1pf(__expf(v0));
                        v1 = (v1 > 0.f) ? (v1 + log1pf(__expf(-v1))) : log1pf(__expf(v1));
                    } else if (EPI == 3) {
                        v0 = 0.5f * v0 * (1.f + erff(v0 * 0.70710678118654752f));
                        v1 = 0.5f * v1 * (1.f + erff(v1 * 0.70710678118654752f));
                    } else {
                        v0 = v0 / (1.f + __expf(-v0));
                        v1 = v1 / (1.f + __expf(-v1));
                    }
                    __nv_bfloat16* row1 = C3 + (size_t)m * c3N;
                    *(uint32_t*)(row1 + n) = pkf2(v0, v1);
                } else {
                    *(float2*)(C + (size_t)orow * ldc + n) = make_float2(v0, v1);
                }
            }
        }
    }
}

// ================= fused weight prep (all conversions + A) =================
__global__ void prep(const float* __restrict__ inpw, const float* __restrict__ xpw,
                     const float* __restrict__ dtw, const float* __restrict__ outw,
                     const float* __restrict__ fw1, const float* __restrict__ fw2,
                     const float* __restrict__ alog)
{
    int idx = blockIdx.x * blockDim.x + threadIdx.x;
    const int N0 = 1024 * 1024;  // xm [hi|hi]
    const int N1 = 64 * 1024;    // x_proj plain
    const int N2 = 1024 * 64;    // dt [w|0]
    const int N3 = 1024 * 512;   // z plain
    const int N4 = 512 * 1024;   // out_proj plain
    const int N5 = 1024 * 512;   // ffn1^T
    const int N6 = 512 * 1024;   // ffn2^T
    const int N7 = DIN * DST;    // An
    unsigned short h, l;
    if (idx < N0) {
        int n = idx >> 10, c = idx & 1023;
        int k = (c < 512) ? c : (c - 512);
        bsplit(inpw[(size_t)n * 512 + k], h, l);
        g_xmw2[idx] = __ushort_as_bfloat16(h);
    } else if ((idx -= N0) < N1) {
        g_xpw1[idx] = __float2bfloat16(xpw[idx]);
    } else if ((idx -= N1) < N2) {
        int n = idx >> 6, c = idx & 63;
        g_dtw1[idx] = (c < 32) ? __float2bfloat16(dtw[n * 32 + c])
                               : __ushort_as_bfloat16(0);
    } else if ((idx -= N2) < N3) {
        g_zw1[idx] = __float2bfloat16(inpw[(size_t)1024 * 512 + idx]);
    } else if ((idx -= N3) < N4) {
        g_outw1[idx] = __float2bfloat16(outw[idx]);
    } else if ((idx -= N4) < N5) {
        int n = idx / 512, k = idx - n * 512;
        g_fw11[idx] = __float2bfloat16(fw1[(size_t)k * 1024 + n]);
    } else if ((idx -= N5) < N6) {
        int n = idx / 1024, k = idx - n * 1024;
        g_fw21[idx] = __float2bfloat16(fw2[(size_t)k * 512 + n]);
    } else if ((idx -= N6) < N7) {
        g_An[idx] = -__expf(alog[idx]);
    }
}

// split-K reduce (2 partials in g_x1 scratch) + fused dt-input packing
__global__ void reduce2_kernel()
{
    int i = blockIdx.x * blockDim.x + threadIdx.x;   // NPTS*64
    const float* p = g_x1;
    const int S = NPTS * 64;
    float v = p[i] + p[i + S];
    g_dbc[i] = v;
    int t = i >> 6, c = i & 63;
    __nv_bfloat16* row = g_dta1 + (size_t)t * 64;
    if (c < 32) {
        row[c]      = __float2bfloat16(v);
        row[32 + c] = __ushort_as_bfloat16(0);
    }
}

// ================= LayerNorm (+gather), segs=2 -> [hi|lo], segs=1 -> bf16 =================
__global__ __launch_bounds__(128) void ln_kernel(
    const float* __restrict__ in, const int* __restrict__ gidx,
    const float* __restrict__ w, const float* __restrict__ b,
    __nv_bfloat16* __restrict__ outb, int segs)
{
    int row = blockIdx.x;
    int src = gidx ? gidx[row] : row;
    float4 v = *((const float4*)(in + (size_t)src * CD) + threadIdx.x);
    float s  = v.x + v.y + v.z + v.w;
    float ss = v.x*v.x + v.y*v.y + v.z*v.z + v.w*v.w;
#pragma unroll
    for (int o = 16; o; o >>= 1) {
        s  += __shfl_xor_sync(0xffffffffu, s,  o);
        ss += __shfl_xor_sync(0xffffffffu, ss, o);
    }
    __shared__ float sh[10];
    if ((threadIdx.x & 31) == 0) {
        sh[threadIdx.x >> 5] = s;
        sh[4 + (threadIdx.x >> 5)] = ss;
    }
    __syncthreads();
    if (threadIdx.x == 0) {
        float S  = sh[0] + sh[1] + sh[2] + sh[3];
        float SS = sh[4] + sh[5] + sh[6] + sh[7];
        float mu = S * (1.f / CD);
        float var = SS * (1.f / CD) - mu * mu;
        sh[8] = mu;
        sh[9] = rsqrtf(var + 1e-5f);
    }
    __syncthreads();
    float mu = sh[8], r = sh[9];
    float4 wv = *((const float4*)w + threadIdx.x);
    float4 bv = *((const float4*)b + threadIdx.x);
    float o[4];
    o[0] = (v.x - mu) * r * wv.x + bv.x;
    o[1] = (v.y - mu) * r * wv.y + bv.y;
    o[2] = (v.z - mu) * r * wv.z + bv.z;
    o[3] = (v.w - mu) * r * wv.w + bv.w;
    unsigned short h[4], l[4];
#pragma unroll
    for (int j = 0; j < 4; j++) bsplit(o[j], h[j], l[j]);
    uint2 wh = make_uint2(pk2(h[0], h[1]), pk2(h[2], h[3]));
    __nv_bfloat16* rowp = outb + (size_t)row * (segs * CD) + 4 * threadIdx.x;
    *(uint2*)(rowp) = wh;
    if (segs == 2) {
        uint2 wl = make_uint2(pk2(l[0], l[1]), pk2(l[2], l[3]));
        *(uint2*)(rowp + CD) = wl;
    }
}

// ================= conv1d (k=4) + SiLU -> xc1 (plain bf16) =================
__global__ void conv_silu_kernel(const float* __restrict__ cw, const float* __restrict__ cb)
{
    int idx = blockIdx.x * blockDim.x + threadIdx.x;
    int t = idx >> 10, d = idx & 1023;
    float acc = cb[d];
#pragma unroll
    for (int k = 0; k < 4; k++) {
        int tt = t - 3 + k;
        if (tt >= 0) acc = fmaf(g_xm[(size_t)tt * DIN + d], cw[d * 4 + k], acc);
    }
    float sg = 1.f / (1.f + __expf(-acc));
    g_xc1[idx] = __float2bfloat16(acc * sg);
}

// ================= chunked selective scan =================
__device__ __forceinline__ bool a_struct_fast(const float* Av)
{
    bool fast = true;
#pragma unroll
    for (int s = 1; s < DST; s++)
        fast = fast && (fabsf(Av[s] - (float)(s + 1) * Av[0]) <= 1e-3f * fabsf(Av[s]));
    return fast;
}
__device__ __forceinline__ void powers16(float p, float* a)
{
    float p2 = p * p, p4 = p2 * p2, p8 = p4 * p4;
    a[0] = p;        a[1] = p2;       a[2] = p2 * p;   a[3] = p4;
    a[4] = p4 * p;   a[5] = p4 * p2;  a[6] = p4 * a[2]; a[7] = p8;
    a[8] = p8 * p;   a[9] = p8 * p2;  a[10] = p8 * a[2]; a[11] = p8 * p4;
    a[12] = p8 * a[4]; a[13] = p8 * a[5]; a[14] = p8 * a[6]; a[15] = p8 * p8;
}
__device__ __forceinline__ float xc_at(int t, int d)
{
    return __bfloat162float(g_xc1[(size_t)t * DIN + d]);
}
__device__ __forceinline__ float dt_at(int t, int d)
{
    return __bfloat162float(g_dt1[(size_t)t * DIN + d]);
}

// pass1: chunk summaries only (final state Hc, sum dt)
__global__ __launch_bounds__(128) void scan_pass1_kernel()
{
    int d = blockIdx.x * 128 + threadIdx.x;
    int c = blockIdx.y;
    int t0 = c * TCH;
    __shared__ float Bsh[TCH][DST];
    for (int i = threadIdx.x; i < TCH * DST; i += 128) {
        int t = i >> 4, s = i & 15;
        Bsh[t][s] = g_dbc[(size_t)(t0 + t) * DBCW + 32 + s];
    }
    __syncthreads();
    float Av[DST], h[DST];
#pragma unroll
    for (int s = 0; s < DST; s++) { Av[s] = g_An[d * DST + s]; h[s] = 0.f; }
    float dts = 0.f;
    if (a_struct_fast(Av)) {
        for (int t = 0; t < TCH; t++) {
            float dtv = dt_at(t0 + t, d);
            float dtx = dtv * xc_at(t0 + t, d);
            dts += dtv;
            float a[DST];
            powers16(__expf(dtv * Av[0]), a);
#pragma unroll
            for (int s = 0; s < DST; s++)
                h[s] = fmaf(a[s], h[s], dtx * Bsh[t][s]);
        }
    } else {
        for (int t = 0; t < TCH; t++) {
            float dtv = dt_at(t0 + t, d);
            float dtx = dtv * xc_at(t0 + t, d);
            dts += dtv;
#pragma unroll
            for (int s = 0; s < DST; s++)
                h[s] = fmaf(__expf(dtv * Av[s]), h[s], dtx * Bsh[t][s]);
        }
    }
#pragma unroll
    for (int s = 0; s < DST; s++)
        g_Hc[((size_t)c * DIN + d) * DST + s] = h[s];
    g_sd[(size_t)c * DIN + d] = dts;
}

__global__ void scan_combine_kernel()
{
    int idx = blockIdx.x * blockDim.x + threadIdx.x;
    int d = idx >> 4;
    float Av = g_An[idx];
    float h = 0.f;
    g_hi[idx] = 0.f;
    for (int c = 1; c < NCH; c++) {
        h = fmaf(__expf(Av * g_sd[(size_t)(c - 1) * DIN + d]), h,
                 g_Hc[(size_t)(c - 1) * DIN * DST + idx]);
        g_hi[(size_t)c * DIN * DST + idx] = h;
    }
}

// pass2: full recurrence from h_init + fused gate -> y1 (bf16)
__global__ __launch_bounds__(128) void scan_pass2_kernel(const float* __restrict__ Dskip)
{
    int d = blockIdx.x * 128 + threadIdx.x;
    int c = blockIdx.y;
    int t0 = c * TCH;
    __shared__ float Bsh[TCH][DST];
    __shared__ float Csh[TCH][DST];
    for (int i = threadIdx.x; i < TCH * DST; i += 128) {
        int t = i >> 4, s = i & 15;
        Bsh[t][s] = g_dbc[(size_t)(t0 + t) * DBCW + 32 + s];
        Csh[t][s] = g_dbc[(size_t)(t0 + t) * DBCW + 48 + s];
    }
    __syncthreads();
    float Av[DST], h[DST];
#pragma unroll
    for (int s = 0; s < DST; s++) {
        Av[s] = g_An[d * DST + s];
        h[s]  = g_hi[(size_t)c * DIN * DST + d * DST + s];
    }
    float Dv = Dskip[d];
    bool fast = a_struct_fast(Av);
    for (int t = 0; t < TCH; t++) {
        float dtv = dt_at(t0 + t, d);
        float xv  = xc_at(t0 + t, d);
        float dtx = dtv * xv;
        float y = 0.f;
        if (fast) {
            float a[DST];
            powers16(__expf(dtv * Av[0]), a);
#pragma unroll
            for (int s = 0; s < DST; s++) {
                h[s] = fmaf(a[s], h[s], dtx * Bsh[t][s]);
                y = fmaf(h[s], Csh[t][s], y);
            }
        } else {
#pragma unroll
            for (int s = 0; s < DST; s++) {
                h[s] = fmaf(__expf(dtv * Av[s]), h[s], dtx * Bsh[t][s]);
                y = fmaf(h[s], Csh[t][s], y);
            }
        }
        float sg = __bfloat162float(g_z1[(size_t)(t0 + t) * DIN + d]);
        float val = (y + xv * Dv) * sg;
        g_y1[(size_t)(t0 + t) * DIN + d] = __float2bfloat16(val);
    }
}

// ================= launch =================
extern "C" void kernel_launch(void* const* d_in, const int* in_sizes, int n_in,
                              void* d_out, int out_size)
{
    (void)in_sizes; (void)n_in; (void)out_size;
    const float* feat  = (const float*)d_in[0];
    const int*   order = (const int*)  d_in[1];
    const float* ln1w  = (const float*)d_in[3];
    const float* ln1b  = (const float*)d_in[4];
    const float* inpw  = (const float*)d_in[5];
    const float* convw = (const float*)d_in[6];
    const float* convb = (const float*)d_in[7];
    const float* xpw   = (const float*)d_in[8];
    const float* dtw   = (const float*)d_in[9];
    const float* dtb   = (const float*)d_in[10];
    const float* alog  = (const float*)d_in[11];
    const float* dskip = (const float*)d_in[12];
    const float* outw  = (const float*)d_in[13];
    const float* ln2w  = (const float*)d_in[14];
    const float* ln2b  = (const float*)d_in[15];
    const float* fw1   = (const float*)d_in[16];
    const float* fb1   = (const float*)d_in[17];
    const float* fw2   = (const float*)d_in[18];
    const float* fb2   = (const float*)d_in[19];
    float* out = (float*)d_out;

    const int SM128 = 3 * (128 + 128) * 128 + 1024;  // 99328
    const int SM64  = 3 * (128 + 64)  * 128 + 1024;  // 74752
    cudaFuncSetAttribute(tgemm<128,0,1>, cudaFuncAttributeMaxDynamicSharedMemorySize, SM128);
    cudaFuncSetAttribute(tgemm<64,0,2>,  cudaFuncAttributeMaxDynamicSharedMemorySize, SM64);
    cudaFuncSetAttribute(tgemm<128,1,1>, cudaFuncAttributeMaxDynamicSharedMemorySize, SM128);
    cudaFuncSetAttribute(tgemm<128,3,1>, cudaFuncAttributeMaxDynamicSharedMemorySize, SM128);
    cudaFuncSetAttribute(tgemm<128,4,1>, cudaFuncAttributeMaxDynamicSharedMemorySize, SM128);
    cudaFuncSetAttribute(tgemm<128,5,1>, cudaFuncAttributeMaxDynamicSharedMemorySize, SM128);
    cudaFuncSetAttribute(tgemm<128,6,1>, cudaFuncAttributeMaxDynamicSharedMemorySize, SM128);

    void *pxm, *px1;
    void *pu2, *pxc1, *pdta1, *pdt1, *pz1, *py1, *ph21, *pg1;
    void *pw0, *pwz, *pw1, *pw2, *pw3, *pw4, *pw5;
    cudaGetSymbolAddress(&pxm,  g_xm);
    cudaGetSymbolAddress(&px1,  g_x1);
    cudaGetSymbolAddress(&pu2,  g_u2);
    cudaGetSymbolAddress(&pxc1, g_xc1);
    cudaGetSymbolAddress(&pdta1,g_dta1);
    cudaGetSymbolAddress(&pdt1, g_dt1);
    cudaGetSymbolAddress(&pz1,  g_z1);
    cudaGetSymbolAddress(&py1,  g_y1);
    cudaGetSymbolAddress(&ph21, g_h21);
    cudaGetSymbolAddress(&pg1,  g_g1);
    cudaGetSymbolAddress(&pw0,  g_xmw2);
    cudaGetSymbolAddress(&pwz,  g_zw1);
    cudaGetSymbolAddress(&pw1,  g_xpw1);
    cudaGetSymbolAddress(&pw2,  g_dtw1);
    cudaGetSymbolAddress(&pw3,  g_outw1);
    cudaGetSymbolAddress(&pw4,  g_fw11);
    cudaGetSymbolAddress(&pw5,  g_fw21);

    // [0] fused weight prep
    prep<<<12853, 256>>>(inpw, xpw, dtw, outw, fw1, fw2, alog);
    // [1] gather + LN1 -> u2 (bf16 [hi|lo])
    ln_kernel<<<NPTS, 128>>>(feat, order, ln1w, ln1b, (__nv_bfloat16*)pu2, 2);
    // [2] xm = u @ in_proj_xm^T  (K=1024: [ah|al]·[bh|bh]) -> g_xm
    tgemm<128,0,1><<<dim3(8,128), 256, SM128>>>((__nv_bfloat16*)pu2, 1024, (__nv_bfloat16*)pw0, 1024, 1024,
                                                (float*)pxm, DIN, nullptr, nullptr, nullptr, nullptr, 0);
    // [3] z1 = silu(u @ in_proj_z^T) -> bf16   <-- ncu capture target
    tgemm<128,5,1><<<dim3(8,128), 256, SM128>>>((__nv_bfloat16*)pu2, 1024, (__nv_bfloat16*)pwz, 512, 512,
                                                nullptr, DIN, nullptr, nullptr, nullptr, (__nv_bfloat16*)pz1, DIN);
    // [4] conv + SiLU -> xc1 (plain bf16)
    conv_silu_kernel<<<(NPTS*DIN)/256, 256>>>(convw, convb);
    // [5] dbc partials = xc @ x_proj^T  (plain bf16, split-K x2 -> g_x1 scratch)
    tgemm<64,0,2><<<dim3(1,128,2), 256, SM64>>>((__nv_bfloat16*)pxc1, 1024, (__nv_bfloat16*)pw1, 1024, 1024,
                                                (float*)px1, DBCW, nullptr, nullptr, nullptr, nullptr, 0);
    // [6] reduce partials -> dbc (+ fused dt-input packing)
    reduce2_kernel<<<(NPTS*DBCW)/256, 256>>>();
    // [7] dt1 = softplus(dbc[:, :32] @ dt_proj^T + b) -> bf16  (K=64)
    tgemm<128,1,1><<<dim3(8,128), 256, SM128>>>((__nv_bfloat16*)pdta1, 64, (__nv_bfloat16*)pw2, 64, 64,
                                                nullptr, DIN, dtb, nullptr, nullptr, (__nv_bfloat16*)pdt1, DIN);
    // [8-10] chunked selective scan
    scan_pass1_kernel<<<dim3(DIN/128, NCH), 128>>>();
    scan_combine_kernel<<<(DIN*DST)/256, 256>>>();
    scan_pass2_kernel<<<dim3(DIN/128, NCH), 128>>>(dskip);
    // [11] x1 = feat[order[m]] + y @ out_proj^T  (gathered residual, fp32)
    tgemm<128,6,1><<<dim3(4,128), 256, SM128>>>((__nv_bfloat16*)py1, 1024, (__nv_bfloat16*)pw3, 1024, 1024,
                                                (float*)px1, CD, nullptr, feat, order, nullptr, 0);
    // [12] h2 = LN2(x1) -> plain bf16
    ln_kernel<<<NPTS, 128>>>((const float*)px1, nullptr, ln2w, ln2b, (__nv_bfloat16*)ph21, 1);
    // [13] g = gelu(h2 @ ffn_w1 + b1) -> plain bf16
    tgemm<128,3,1><<<dim3(8,128), 256, SM128>>>((__nv_bfloat16*)ph21, 512, (__nv_bfloat16*)pw4, 512, 512,
                                                nullptr, MLPD, fb1, nullptr, nullptr, (__nv_bfloat16*)pg1, MLPD);
    // [14] out[order[m]] = x1[m] + g @ ffn_w2 + b2  (fused residual + scatter)
    tgemm<128,4,1><<<dim3(4,128), 256, SM128>>>((__nv_bfloat16*)pg1, 1024, (__nv_bfloat16*)pw5, 1024, 1024,
                                                out, CD, fb2, (const float*)px1, order, nullptr, 0);
}

// round 17
// speedup vs baseline: 1.2373x; 1.0682x over previous
#include <cuda_runtime.h>
#include <cuda_bf16.h>
#include <math.h>
#include <stdint.h>

#define NPTS 16384
#define CD   512
#define DIN  1024
#define DST  16
#define DBCW 64
#define MLPD 1024
#define NCH  128
#define TCH  128

// ================= scratch =================
__device__ __align__(16) float g_dbc[NPTS*DBCW];
__device__ __align__(16) float g_x1 [NPTS*CD];    // also split-K scratch for x_proj partials
__device__ __align__(16) float g_An [DIN*DST];
__device__ __align__(16) float g_Hc [NCH*DIN*DST];
__device__ __align__(16) float g_sd [NCH*DIN];
__device__ __align__(16) float g_hi [NCH*DIN*DST];
// bf16 activations
__device__ __align__(16) __nv_bfloat16 g_u1  [NPTS*CD];      // LN1 out, plain bf16
__device__ __align__(16) __nv_bfloat16 g_xmz1[NPTS*2048];    // [xm | silu(z)] interleaved, bf16
__device__ __align__(16) __nv_bfloat16 g_xc1 [NPTS*DIN];     // plain bf16
__device__ __align__(16) __nv_bfloat16 g_dta1[NPTS*64];      // [dbc[:,0:32] bf16 | 0]
__device__ __align__(16) __nv_bfloat16 g_dt1 [NPTS*DIN];     // softplus(dt) bf16
__device__ __align__(16) __nv_bfloat16 g_y1  [NPTS*DIN];
__device__ __align__(16) __nv_bfloat16 g_h21 [NPTS*CD];
__device__ __align__(16) __nv_bfloat16 g_g1  [NPTS*MLPD];
// weights (plain bf16)
__device__ __align__(16) __nv_bfloat16 g_izw  [2048*512];    // full in_proj
__device__ __align__(16) __nv_bfloat16 g_xpw1 [64*1024];
__device__ __align__(16) __nv_bfloat16 g_dtw1 [1024*64];     // [w bf16 | 0]
__device__ __align__(16) __nv_bfloat16 g_outw1[512*1024];
__device__ __align__(16) __nv_bfloat16 g_fw11 [1024*512];
__device__ __align__(16) __nv_bfloat16 g_fw21 [512*1024];

// ================= helpers =================
__device__ __forceinline__ uint32_t smem_u32(const void* p) {
    uint32_t a;
    asm("{ .reg .u64 t; cvta.to.shared.u64 t, %1; cvt.u32.u64 %0, t; }" : "=r"(a) : "l"(p));
    return a;
}
__device__ __forceinline__ void cp16(uint32_t dst, const void* src) {
    asm volatile("cp.async.cg.shared.global [%0], [%1], 16;" :: "r"(dst), "l"(src) : "memory");
}
#define CP_COMMIT() asm volatile("cp.async.commit_group;" ::: "memory")
#define CP_WAIT(n)  asm volatile("cp.async.wait_group %0;" :: "n"(n) : "memory")
#define LDSM4(r0, r1, r2, r3, addr) \
    asm volatile("ldmatrix.sync.aligned.m8n8.x4.shared.b16 {%0,%1,%2,%3}, [%4];" \
        : "=r"(r0), "=r"(r1), "=r"(r2), "=r"(r3) : "r"(addr))
#define MMA16816(c, a, b) \
    asm volatile("mma.sync.aligned.m16n8k16.row.col.f32.bf16.bf16.f32 " \
        "{%0,%1,%2,%3}, {%4,%5,%6,%7}, {%8,%9}, {%0,%1,%2,%3};" \
        : "+f"((c)[0]), "+f"((c)[1]), "+f"((c)[2]), "+f"((c)[3]) \
        : "r"((a)[0]), "r"((a)[1]), "r"((a)[2]), "r"((a)[3]), "r"((b)[0]), "r"((b)[1]))

__device__ __forceinline__ uint32_t swz(uint32_t off) { return off ^ ((off >> 3) & 0x70); }
__device__ __forceinline__ void bsplit(float x, unsigned short& h, unsigned short& l) {
    __nv_bfloat16 hb = __float2bfloat16(x);
    __nv_bfloat16 lb = __float2bfloat16(x - __bfloat162float(hb));
    h = __bfloat16_as_ushort(hb);
    l = __bfloat16_as_ushort(lb);
}
__device__ __forceinline__ uint32_t pk2(unsigned short a, unsigned short b) {
    return (uint32_t)a | ((uint32_t)b << 16);
}
__device__ __forceinline__ uint32_t pkf2(float a, float b) {
    return pk2(__bfloat16_as_ushort(__float2bfloat16(a)),
               __bfloat16_as_ushort(__float2bfloat16(b)));
}

// ================= bf16 tensor-core GEMM (mma.sync HMMA), 3-stage pipeline =================
// C[16384, Nn] = A @ B^T over K3 cols. SPLITK via blockIdx.z (contiguous K partitions).
// EPI: 0 fp32 | 1 bias+softplus->bf16 | 3 bias+gelu->bf16 | 4 bias+res+scatter |
//      6 gathered-res fp32 | 7 merged in_proj: n<1024 -> bf16, n>=1024 -> silu->bf16
template<int BN, int EPI, int SPLITK>
__global__ __launch_bounds__(256) void tgemm(
    const __nv_bfloat16* __restrict__ A, int lda,
    const __nv_bfloat16* __restrict__ B, int ldb, int K3,
    float* __restrict__ C, int ldc,
    const float* __restrict__ bias, const float* __restrict__ res,
    const int* __restrict__ gmap, __nv_bfloat16* __restrict__ C3, int c3N)
{
    constexpr int WN  = BN / 2;
    constexpr int NT8 = WN / 8;
    constexpr int STAGE = (128 + BN) * 128;

    extern __shared__ char dsm[];
    uint32_t base = (smem_u32(dsm) + 1023) & ~1023u;

    const int tid = threadIdx.x;
    const int wid = tid >> 5, lid = tid & 31;
    const int m0 = blockIdx.y * 128;
    const int n0 = blockIdx.x * BN;
    const int wm = (wid >> 1) * 32;
    const int wn = (wid & 1) * WN;
    const int Kc = K3 / SPLITK;
    const int KB = Kc >> 6;
    if (SPLITK > 1) {
        int kz = blockIdx.z;
        A += kz * Kc;
        B += kz * Kc;
        C += (size_t)kz * NPTS * ldc;
    }

    float acc[2][NT8][4];
#pragma unroll
    for (int mt = 0; mt < 2; mt++)
#pragma unroll
        for (int nt = 0; nt < NT8; nt++)
#pragma unroll
            for (int j = 0; j < 4; j++) acc[mt][nt][j] = 0.f;

    auto load_stage = [&](int kb, int buf) {
        uint32_t sA = base + buf * STAGE;
        uint32_t sB = sA + 16384;
        const __nv_bfloat16* Ab = A + (size_t)m0 * lda + kb * 64;
        const __nv_bfloat16* Bb = B + (size_t)n0 * ldb + kb * 64;
#pragma unroll
        for (int i = tid; i < 1024; i += 256) {
            int row = i >> 3, c = i & 7;
            uint32_t off = (row << 7) + (c << 4);
            cp16(sA + swz(off), Ab + (size_t)row * lda + c * 8);
        }
#pragma unroll
        for (int i = tid; i < BN * 8; i += 256) {
            int row = i >> 3, c = i & 7;
            uint32_t off = (row << 7) + (c << 4);
            cp16(sB + swz(off), Bb + (size_t)row * ldb + c * 8);
        }
        CP_COMMIT();
    };

    const int lr = lid & 7, lg = lid >> 3;
    const int rsel = (lg & 1) * 8 + lr;
    const int ksel = (lg >> 1) * 8;

    load_stage(0, 0);
    if (KB > 1) load_stage(1, 1);

    for (int kb = 0; kb < KB; kb++) {
        if (kb + 1 < KB) CP_WAIT(1);
        else             CP_WAIT(0);
        __syncthreads();
        if (kb + 2 < KB) load_stage(kb + 2, (kb + 2) % 3);

        uint32_t sA = base + (kb % 3) * STAGE;
        uint32_t sB = sA + 16384;
#pragma unroll
        for (int ks = 0; ks < 4; ks++) {
            uint32_t a[2][4];
#pragma unroll
            for (int mt = 0; mt < 2; mt++) {
                uint32_t off = (uint32_t)(wm + mt * 16 + rsel) * 128 + (ks * 16 + ksel) * 2;
                LDSM4(a[mt][0], a[mt][1], a[mt][2], a[mt][3], sA + swz(off));
            }
            uint32_t b[NT8][2];
#pragma unroll
            for (int nt2 = 0; nt2 < NT8 / 2; nt2++) {
                uint32_t off = (uint32_t)(wn + nt2 * 16 + rsel) * 128 + (ks * 16 + ksel) * 2;
                uint32_t r0, r1, r2, r3;
                LDSM4(r0, r1, r2, r3, sB + swz(off));
                b[2*nt2][0] = r0; b[2*nt2][1] = r2;
                b[2*nt2+1][0] = r1; b[2*nt2+1][1] = r3;
            }
#pragma unroll
            for (int mt = 0; mt < 2; mt++)
#pragma unroll
                for (int nt = 0; nt < NT8; nt++)
                    MMA16816(acc[mt][nt], a[mt], b[nt]);
        }
    }

    // ---------------- epilogue ----------------
    const int tg = lid >> 2, tq = lid & 3;
#pragma unroll
    for (int mt = 0; mt < 2; mt++) {
#pragma unroll
        for (int half = 0; half < 2; half++) {
            const int m = m0 + wm + mt * 16 + half * 8 + tg;
            const int orow = (EPI == 4) ? gmap[m] : m;
            const int rrow = (EPI == 6) ? gmap[m] : m;
#pragma unroll
            for (int nt = 0; nt < NT8; nt++) {
                const int n = n0 + wn + nt * 8 + tq * 2;
                float v0 = acc[mt][nt][half * 2 + 0];
                float v1 = acc[mt][nt][half * 2 + 1];
                if (EPI == 1 || EPI == 3 || EPI == 4) {
                    float2 bb = *(const float2*)(bias + n);
                    v0 += bb.x; v1 += bb.y;
                }
                if (EPI == 4 || EPI == 6) {
                    float2 rr = *(const float2*)(res + (size_t)rrow * ldc + n);
                    v0 += rr.x; v1 += rr.y;
                }
                if (EPI == 1 || EPI == 3 || EPI == 7) {
                    if (EPI == 1) {
                        v0 = (v0 > 0.f) ? (v0 + log1pf(__expf(-v0))) : log1pf(__expf(v0));
                        v1 = (v1 > 0.f) ? (v1 + log1pf(__expf(-v1))) : log1pf(__expf(v1));
                    } else if (EPI == 3) {
                        v0 = 0.5f * v0 * (1.f + erff(v0 * 0.70710678118654752f));
                        v1 = 0.5f * v1 * (1.f + erff(v1 * 0.70710678118654752f));
                    } else {
                        if (n >= 1024) {           // z half: silu
                            v0 = v0 / (1.f + __expf(-v0));
                            v1 = v1 / (1.f + __expf(-v1));
                        }
                    }
                    __nv_bfloat16* row1 = C3 + (size_t)m * c3N;
                    *(uint32_t*)(row1 + n) = pkf2(v0, v1);
                } else {
                    *(float2*)(C + (size_t)orow * ldc + n) = make_float2(v0, v1);
                }
            }
        }
    }
}

// ================= fused weight prep (all conversions + A) =================
__global__ void prep(const float* __restrict__ inpw, const float* __restrict__ xpw,
                     const float* __restrict__ dtw, const float* __restrict__ outw,
                     const float* __restrict__ fw1, const float* __restrict__ fw2,
                     const float* __restrict__ alog)
{
    int idx = blockIdx.x * blockDim.x + threadIdx.x;
    const int N0 = 2048 * 512;   // full in_proj plain bf16
    const int N1 = 64 * 1024;    // x_proj plain
    const int N2 = 1024 * 64;    // dt [w|0]
    const int N3 = 512 * 1024;   // out_proj plain
    const int N4 = 1024 * 512;   // ffn1^T
    const int N5 = 512 * 1024;   // ffn2^T
    const int N6 = DIN * DST;    // An
    if (idx < N0) {
        g_izw[idx] = __float2bfloat16(inpw[idx]);
    } else if ((idx -= N0) < N1) {
        g_xpw1[idx] = __float2bfloat16(xpw[idx]);
    } else if ((idx -= N1) < N2) {
        int n = idx >> 6, c = idx & 63;
        g_dtw1[idx] = (c < 32) ? __float2bfloat16(dtw[n * 32 + c])
                               : __ushort_as_bfloat16(0);
    } else if ((idx -= N2) < N3) {
        g_outw1[idx] = __float2bfloat16(outw[idx]);
    } else if ((idx -= N3) < N4) {
        int n = idx / 512, k = idx - n * 512;
        g_fw11[idx] = __float2bfloat16(fw1[(size_t)k * 1024 + n]);
    } else if ((idx -= N4) < N5) {
        int n = idx / 1024, k = idx - n * 1024;
        g_fw21[idx] = __float2bfloat16(fw2[(size_t)k * 512 + n]);
    } else if ((idx -= N5) < N6) {
        g_An[idx] = -__expf(alog[idx]);
    }
}

// split-K reduce (2 partials in g_x1 scratch) + fused dt-input packing
__global__ void reduce2_kernel()
{
    int i = blockIdx.x * blockDim.x + threadIdx.x;   // NPTS*64
    const float* p = g_x1;
    const int S = NPTS * 64;
    float v = p[i] + p[i + S];
    g_dbc[i] = v;
    int t = i >> 6, c = i & 63;
    __nv_bfloat16* row = g_dta1 + (size_t)t * 64;
    if (c < 32) {
        row[c]      = __float2bfloat16(v);
        row[32 + c] = __ushort_as_bfloat16(0);
    }
}

// ================= LayerNorm (+gather) -> plain bf16 =================
__global__ __launch_bounds__(128) void ln_kernel(
    const float* __restrict__ in, const int* __restrict__ gidx,
    const float* __restrict__ w, const float* __restrict__ b,
    __nv_bfloat16* __restrict__ outb)
{
    int row = blockIdx.x;
    int src = gidx ? gidx[row] : row;
    float4 v = *((const float4*)(in + (size_t)src * CD) + threadIdx.x);
    float s  = v.x + v.y + v.z + v.w;
    float ss = v.x*v.x + v.y*v.y + v.z*v.z + v.w*v.w;
#pragma unroll
    for (int o = 16; o; o >>= 1) {
        s  += __shfl_xor_sync(0xffffffffu, s,  o);
        ss += __shfl_xor_sync(0xffffffffu, ss, o);
    }
    __shared__ float sh[10];
    if ((threadIdx.x & 31) == 0) {
        sh[threadIdx.x >> 5] = s;
        sh[4 + (threadIdx.x >> 5)] = ss;
    }
    __syncthreads();
    if (threadIdx.x == 0) {
        float S  = sh[0] + sh[1] + sh[2] + sh[3];
        float SS = sh[4] + sh[5] + sh[6] + sh[7];
        float mu = S * (1.f / CD);
        float var = SS * (1.f / CD) - mu * mu;
        sh[8] = mu;
        sh[9] = rsqrtf(var + 1e-5f);
    }
    __syncthreads();
    float mu = sh[8], r = sh[9];
    float4 wv = *((const float4*)w + threadIdx.x);
    float4 bv = *((const float4*)b + threadIdx.x);
    float o[4];
    o[0] = (v.x - mu) * r * wv.x + bv.x;
    o[1] = (v.y - mu) * r * wv.y + bv.y;
    o[2] = (v.z - mu) * r * wv.z + bv.z;
    o[3] = (v.w - mu) * r * wv.w + bv.w;
    __nv_bfloat16* rowp = outb + (size_t)row * CD + 4 * threadIdx.x;
    *(uint2*)(rowp) = make_uint2(pkf2(o[0], o[1]), pkf2(o[2], o[3]));
}

// ================= conv1d (k=4) + SiLU -> xc1 (plain bf16) =================
__global__ void conv_silu_kernel(const float* __restrict__ cw, const float* __restrict__ cb)
{
    int idx = blockIdx.x * blockDim.x + threadIdx.x;
    int t = idx >> 10, d = idx & 1023;
    float acc = cb[d];
#pragma unroll
    for (int k = 0; k < 4; k++) {
        int tt = t - 3 + k;
        if (tt >= 0)
            acc = fmaf(__bfloat162float(g_xmz1[(size_t)tt * 2048 + d]), cw[d * 4 + k], acc);
    }
    float sg = 1.f / (1.f + __expf(-acc));
    g_xc1[idx] = __float2bfloat16(acc * sg);
}

// ================= chunked selective scan =================
__device__ __forceinline__ bool a_struct_fast(const float* Av)
{
    bool fast = true;
#pragma unroll
    for (int s = 1; s < DST; s++)
        fast = fast && (fabsf(Av[s] - (float)(s + 1) * Av[0]) <= 1e-3f * fabsf(Av[s]));
    return fast;
}
__device__ __forceinline__ void powers16(float p, float* a)
{
    float p2 = p * p, p4 = p2 * p2, p8 = p4 * p4;
    a[0] = p;        a[1] = p2;       a[2] = p2 * p;   a[3] = p4;
    a[4] = p4 * p;   a[5] = p4 * p2;  a[6] = p4 * a[2]; a[7] = p8;
    a[8] = p8 * p;   a[9] = p8 * p2;  a[10] = p8 * a[2]; a[11] = p8 * p4;
    a[12] = p8 * a[4]; a[13] = p8 * a[5]; a[14] = p8 * a[6]; a[15] = p8 * p8;
}
__device__ __forceinline__ float xc_at(int t, int d)
{
    return __bfloat162float(g_xc1[(size_t)t * DIN + d]);
}
__device__ __forceinline__ float dt_at(int t, int d)
{
    return __bfloat162float(g_dt1[(size_t)t * DIN + d]);
}

// pass1: chunk summaries only (final state Hc, sum dt)
__global__ __launch_bounds__(128) void scan_pass1_kernel()
{
    int d = blockIdx.x * 128 + threadIdx.x;
    int c = blockIdx.y;
    int t0 = c * TCH;
    __shared__ float Bsh[TCH][DST];
    for (int i = threadIdx.x; i < TCH * DST; i += 128) {
        int t = i >> 4, s = i & 15;
        Bsh[t][s] = g_dbc[(size_t)(t0 + t) * DBCW + 32 + s];
    }
    __syncthreads();
    float Av[DST], h[DST];
#pragma unroll
    for (int s = 0; s < DST; s++) { Av[s] = g_An[d * DST + s]; h[s] = 0.f; }
    float dts = 0.f;
    if (a_struct_fast(Av)) {
        for (int t = 0; t < TCH; t++) {
            float dtv = dt_at(t0 + t, d);
            float dtx = dtv * xc_at(t0 + t, d);
            dts += dtv;
            float a[DST];
            powers16(__expf(dtv * Av[0]), a);
#pragma unroll
            for (int s = 0; s < DST; s++)
                h[s] = fmaf(a[s], h[s], dtx * Bsh[t][s]);
        }
    } else {
        for (int t = 0; t < TCH; t++) {
            float dtv = dt_at(t0 + t, d);
            float dtx = dtv * xc_at(t0 + t, d);
            dts += dtv;
#pragma unroll
            for (int s = 0; s < DST; s++)
                h[s] = fmaf(__expf(dtv * Av[s]), h[s], dtx * Bsh[t][s]);
        }
    }
#pragma unroll
    for (int s = 0; s < DST; s++)
        g_Hc[((size_t)c * DIN + d) * DST + s] = h[s];
    g_sd[(size_t)c * DIN + d] = dts;
}

__global__ void scan_combine_kernel()
{
    int idx = blockIdx.x * blockDim.x + threadIdx.x;
    int d = idx >> 4;
    float Av = g_An[idx];
    float h = 0.f;
    g_hi[idx] = 0.f;
    for (int c = 1; c < NCH; c++) {
        h = fmaf(__expf(Av * g_sd[(size_t)(c - 1) * DIN + d]), h,
                 g_Hc[(size_t)(c - 1) * DIN * DST + idx]);
        g_hi[(size_t)c * DIN * DST + idx] = h;
    }
}

// pass2: full recurrence from h_init + fused gate -> y1 (bf16)
__global__ __launch_bounds__(128) void scan_pass2_kernel(const float* __restrict__ Dskip)
{
    int d = blockIdx.x * 128 + threadIdx.x;
    int c = blockIdx.y;
    int t0 = c * TCH;
    __shared__ float Bsh[TCH][DST];
    __shared__ float Csh[TCH][DST];
    for (int i = threadIdx.x; i < TCH * DST; i += 128) {
        int t = i >> 4, s = i & 15;
        Bsh[t][s] = g_dbc[(size_t)(t0 + t) * DBCW + 32 + s];
        Csh[t][s] = g_dbc[(size_t)(t0 + t) * DBCW + 48 + s];
    }
    __syncthreads();
    float Av[DST], h[DST];
#pragma unroll
    for (int s = 0; s < DST; s++) {
        Av[s] = g_An[d * DST + s];
        h[s]  = g_hi[(size_t)c * DIN * DST + d * DST + s];
    }
    float Dv = Dskip[d];
    bool fast = a_struct_fast(Av);
    for (int t = 0; t < TCH; t++) {
        float dtv = dt_at(t0 + t, d);
        float xv  = xc_at(t0 + t, d);
        float dtx = dtv * xv;
        float y = 0.f;
        if (fast) {
            float a[DST];
            powers16(__expf(dtv * Av[0]), a);
#pragma unroll
            for (int s = 0; s < DST; s++) {
                h[s] = fmaf(a[s], h[s], dtx * Bsh[t][s]);
                y = fmaf(h[s], Csh[t][s], y);
            }
        } else {
#pragma unroll
            for (int s = 0; s < DST; s++) {
                h[s] = fmaf(__expf(dtv * Av[s]), h[s], dtx * Bsh[t][s]);
                y = fmaf(h[s], Csh[t][s], y);
            }
        }
        float sg = __bfloat162float(g_xmz1[(size_t)(t0 + t) * 2048 + 1024 + d]);
        float val = (y + xv * Dv) * sg;
        g_y1[(size_t)(t0 + t) * DIN + d] = __float2bfloat16(val);
    }
}

// ================= launch =================
extern "C" void kernel_launch(void* const* d_in, const int* in_sizes, int n_in,
                              void* d_out, int out_size)
{
    (void)in_sizes; (void)n_in; (void)out_size;
    const float* feat  = (const float*)d_in[0];
    const int*   order = (const int*)  d_in[1];
    const float* ln1w  = (const float*)d_in[3];
    const float* ln1b  = (const float*)d_in[4];
    const float* inpw  = (const float*)d_in[5];
    const float* convw = (const float*)d_in[6];
    const float* convb = (const float*)d_in[7];
    const float* xpw   = (const float*)d_in[8];
    const float* dtw   = (const float*)d_in[9];
    const float* dtb   = (const float*)d_in[10];
    const float* alog  = (const float*)d_in[11];
    const float* dskip = (const float*)d_in[12];
    const float* outw  = (const float*)d_in[13];
    const float* ln2w  = (const float*)d_in[14];
    const float* ln2b  = (const float*)d_in[15];
    const float* fw1   = (const float*)d_in[16];
    const float* fb1   = (const float*)d_in[17];
    const float* fw2   = (const float*)d_in[18];
    const float* fb2   = (const float*)d_in[19];
    float* out = (float*)d_out;

    const int SM128 = 3 * (128 + 128) * 128 + 1024;  // 99328
    const int SM64  = 3 * (128 + 64)  * 128 + 1024;  // 74752
    cudaFuncSetAttribute(tgemm<128,7,1>, cudaFuncAttributeMaxDynamicSharedMemorySize, SM128);
    cudaFuncSetAttribute(tgemm<64,0,2>,  cudaFuncAttributeMaxDynamicSharedMemorySize, SM64);
    cudaFuncSetAttribute(tgemm<128,1,1>, cudaFuncAttributeMaxDynamicSharedMemorySize, SM128);
    cudaFuncSetAttribute(tgemm<128,3,1>, cudaFuncAttributeMaxDynamicSharedMemorySize, SM128);
    cudaFuncSetAttribute(tgemm<128,4,1>, cudaFuncAttributeMaxDynamicSharedMemorySize, SM128);
    cudaFuncSetAttribute(tgemm<128,6,1>, cudaFuncAttributeMaxDynamicSharedMemorySize, SM128);

    void *px1;
    void *pu1, *pxmz1, *pxc1, *pdta1, *pdt1, *py1, *ph21, *pg1;
    void *pwi, *pw1, *pw2, *pw3, *pw4, *pw5;
    cudaGetSymbolAddress(&px1,   g_x1);
    cudaGetSymbolAddress(&pu1,   g_u1);
    cudaGetSymbolAddress(&pxmz1, g_xmz1);
    cudaGetSymbolAddress(&pxc1,  g_xc1);
    cudaGetSymbolAddress(&pdta1, g_dta1);
    cudaGetSymbolAddress(&pdt1,  g_dt1);
    cudaGetSymbolAddress(&py1,   g_y1);
    cudaGetSymbolAddress(&ph21,  g_h21);
    cudaGetSymbolAddress(&pg1,   g_g1);
    cudaGetSymbolAddress(&pwi,   g_izw);
    cudaGetSymbolAddress(&pw1,   g_xpw1);
    cudaGetSymbolAddress(&pw2,   g_dtw1);
    cudaGetSymbolAddress(&pw3,   g_outw1);
    cudaGetSymbolAddress(&pw4,   g_fw11);
    cudaGetSymbolAddress(&pw5,   g_fw21);

    // [0] fused weight prep (total elems = 2768896 -> 10816 blocks)
    prep<<<10816, 256>>>(inpw, xpw, dtw, outw, fw1, fw2, alog);
    // [1] gather + LN1 -> u1 (plain bf16)
    ln_kernel<<<NPTS, 128>>>(feat, order, ln1w, ln1b, (__nv_bfloat16*)pu1);
    // [2] [xm | silu(z)] = u @ in_proj^T  (merged, N=2048, K=512, plain bf16) -> g_xmz1
    tgemm<128,7,1><<<dim3(16,128), 256, SM128>>>((__nv_bfloat16*)pu1, 512, (__nv_bfloat16*)pwi, 512, 512,
                                                 nullptr, 0, nullptr, nullptr, nullptr, (__nv_bfloat16*)pxmz1, 2048);
    // [3] conv + SiLU -> xc1 (plain bf16)   <-- ncu capture target
    conv_silu_kernel<<<(NPTS*DIN)/256, 256>>>(convw, convb);
    // [4] dbc partials = xc @ x_proj^T  (plain bf16, split-K x2 -> g_x1 scratch)
    tgemm<64,0,2><<<dim3(1,128,2), 256, SM64>>>((__nv_bfloat16*)pxc1, 1024, (__nv_bfloat16*)pw1, 1024, 1024,
                                                (float*)px1, DBCW, nullptr, nullptr, nullptr, nullptr, 0);
    // [5] reduce partials -> dbc (+ fused dt-input packing)
    reduce2_kernel<<<(NPTS*DBCW)/256, 256>>>();
    // [6] dt1 = softplus(dbc[:, :32] @ dt_proj^T + b) -> bf16  (K=64)
    tgemm<128,1,1><<<dim3(8,128), 256, SM128>>>((__nv_bfloat16*)pdta1, 64, (__nv_bfloat16*)pw2, 64, 64,
                                                nullptr, DIN, dtb, nullptr, nullptr, (__nv_bfloat16*)pdt1, DIN);
    // [7-9] chunked selective scan
    scan_pass1_kernel<<<dim3(DIN/128, NCH), 128>>>();
    scan_combine_kernel<<<(DIN*DST)/256, 256>>>();
    scan_pass2_kernel<<<dim3(DIN/128, NCH), 128>>>(dskip);
    // [10] x1 = feat[order[m]] + y @ out_proj^T  (gathered residual, fp32)
    tgemm<128,6,1><<<dim3(4,128), 256, SM128>>>((__nv_bfloat16*)py1, 1024, (__nv_bfloat16*)pw3, 1024, 1024,
                                                (float*)px1, CD, nullptr, feat, order, nullptr, 0);
    // [11] h2 = LN2(x1) -> plain bf16
    ln_kernel<<<NPTS, 128>>>((const float*)px1, nullptr, ln2w, ln2b, (__nv_bfloat16*)ph21);
    // [12] g = gelu(h2 @ ffn_w1 + b1) -> plain bf16
    tgemm<128,3,1><<<dim3(8,128), 256, SM128>>>((__nv_bfloat16*)ph21, 512, (__nv_bfloat16*)pw4, 512, 512,
                                                nullptr, MLPD, fb1, nullptr, nullptr, (__nv_bfloat16*)pg1, MLPD);
    // [13] out[order[m]] = x1[m] + g @ ffn_w2 + b2  (fused residual + scatter)
    tgemm<128,4,1><<<dim3(4,128), 256, SM128>>>((__nv_bfloat16*)pg1, 1024, (__nv_bfloat16*)pw5, 1024, 1024,
                                                out, CD, fb2, (const float*)px1, order, nullptr, 0);
}